// round 12
// baseline (speedup 1.0000x reference)
#include <cuda_runtime.h>
#include <cuda_bf16.h>
#include <math.h>
#include <stdint.h>

#define SEQ    512
#define BATCH  64
#define D_IN   1024
#define D_H    1024
#define M_IN   (SEQ * BATCH)      // 32768
#define BH     (BATCH * D_H)      // 65536
#define GRID_P 128                // persistent blocks for recurrence
#define NGRP   8                  // barrier tree groups (16 blocks each)

typedef unsigned long long ull;

// packed f32x2 helpers (FFMA2: only reachable via PTX fma.rn.f32x2)
__device__ __forceinline__ ull pk2(float lo, float hi) {
    ull r;
    asm("mov.b64 %0, {%1, %2};" : "=l"(r) : "r"(__float_as_uint(lo)), "r"(__float_as_uint(hi)));
    return r;
}
__device__ __forceinline__ void upk2(float& lo, float& hi, ull v) {
    uint32_t a, b;
    asm("mov.b64 {%0, %1}, %2;" : "=r"(a), "=r"(b) : "l"(v));
    lo = __uint_as_float(a); hi = __uint_as_float(b);
}
__device__ __forceinline__ ull fma2(ull a, ull b, ull c) {
    ull d;
    asm("fma.rn.f32x2 %0, %1, %2, %3;" : "=l"(d) : "l"(a), "l"(b), "l"(c));
    return d;
}

// ===========================================================================
// Persistent device state: two-level barrier counters (reset by GEMM kernel,
// stream-ordered before the rnn kernel; absolute targets each run).
// Group counters in 256B-strided slots -> distinct LTS slices (bit7 is
// transparent in the addr->LTS hash, so 128B stride would pair-collide).
// ===========================================================================
__device__ unsigned g_grp[NGRP * 64];
__device__ unsigned g_root;

// ===========================================================================
// Input projection: out[m][n] = sum_i x[m][i]*Wih[n][i] + bih[n] + bhh[n]
// M=32768, N=1024, K=1024. BM=BN=128, BK=16, 8x8 thread tile, 256 threads.
// Register-prefetch software pipeline hides global-load latency.
// Block (0,0) resets the rnn barrier counters.
// ===========================================================================
__global__ __launch_bounds__(256) void input_gemm_kernel(
    const float* __restrict__ x, const float* __restrict__ Wih,
    const float* __restrict__ bih, const float* __restrict__ bhh,
    float* __restrict__ out)
{
    __shared__ __align__(16) float As[16][132];
    __shared__ __align__(16) float Bs[16][132];

    const int tid = threadIdx.x;
    if (blockIdx.x == 0 && blockIdx.y == 0) {
        if (tid < NGRP) g_grp[tid * 64] = 0u;
        if (tid == NGRP) g_root = 0u;
    }

    const int m0 = blockIdx.y * 128;
    const int n0 = blockIdx.x * 128;
    const int tx = tid & 15;   // -> n
    const int ty = tid >> 4;   // -> m

    // per-thread load coordinates (2 float4 each for A and B per iter)
    int lr[2], lc[2];
    #pragma unroll
    for (int l = 0; l < 2; l++) {
        int f = tid + l * 256;
        lr[l] = f >> 2;
        lc[l] = (f & 3) * 4;
    }

    ull acc2[8][4];
    #pragma unroll
    for (int i = 0; i < 8; i++)
        #pragma unroll
        for (int j = 0; j < 4; j++) acc2[i][j] = 0ull;

    // prologue: prefetch k0 = 0 tile
    float4 pA[2], pB[2];
    #pragma unroll
    for (int l = 0; l < 2; l++) {
        pA[l] = *(const float4*)(x   + (size_t)(m0 + lr[l]) * D_IN + lc[l]);
        pB[l] = *(const float4*)(Wih + (size_t)(n0 + lr[l]) * D_IN + lc[l]);
    }

    for (int k0 = 0; k0 < D_IN; k0 += 16) {
        // stage prefetched tile into smem (transposed)
        #pragma unroll
        for (int l = 0; l < 2; l++) {
            int r = lr[l], c = lc[l];
            As[c + 0][r] = pA[l].x; As[c + 1][r] = pA[l].y;
            As[c + 2][r] = pA[l].z; As[c + 3][r] = pA[l].w;
            Bs[c + 0][r] = pB[l].x; Bs[c + 1][r] = pB[l].y;
            Bs[c + 2][r] = pB[l].z; Bs[c + 3][r] = pB[l].w;
        }
        __syncthreads();

        // prefetch next tile (overlaps with the FMA loop below)
        if (k0 + 16 < D_IN) {
            #pragma unroll
            for (int l = 0; l < 2; l++) {
                pA[l] = *(const float4*)(x   + (size_t)(m0 + lr[l]) * D_IN + k0 + 16 + lc[l]);
                pB[l] = *(const float4*)(Wih + (size_t)(n0 + lr[l]) * D_IN + k0 + 16 + lc[l]);
            }
        }

        #pragma unroll
        for (int k = 0; k < 16; k++) {
            float a[8], b[8];
            *(float4*)&a[0] = *(const float4*)&As[k][ty * 8];
            *(float4*)&a[4] = *(const float4*)&As[k][ty * 8 + 4];
            *(float4*)&b[0] = *(const float4*)&Bs[k][tx * 8];
            *(float4*)&b[4] = *(const float4*)&Bs[k][tx * 8 + 4];
            ull b2[4];
            #pragma unroll
            for (int q = 0; q < 4; q++) b2[q] = pk2(b[2 * q], b[2 * q + 1]);
            #pragma unroll
            for (int i = 0; i < 8; i++) {
                ull a2 = pk2(a[i], a[i]);
                #pragma unroll
                for (int q = 0; q < 4; q++)
                    acc2[i][q] = fma2(a2, b2[q], acc2[i][q]);
            }
        }
        __syncthreads();
    }

    #pragma unroll
    for (int i = 0; i < 8; i++) {
        int m = m0 + ty * 8 + i;
        float accf[8];
        #pragma unroll
        for (int q = 0; q < 4; q++) upk2(accf[2 * q], accf[2 * q + 1], acc2[i][q]);
        #pragma unroll
        for (int j = 0; j < 8; j += 4) {
            int n = n0 + tx * 8 + j;
            float4 o;
            o.x = accf[j + 0] + bih[n + 0] + bhh[n + 0];
            o.y = accf[j + 1] + bih[n + 1] + bhh[n + 1];
            o.z = accf[j + 2] + bih[n + 2] + bhh[n + 2];
            o.w = accf[j + 3] + bih[n + 3] + bhh[n + 3];
            *(float4*)(out + (size_t)m * D_H + n) = o;
        }
    }
}

// ===========================================================================
// Persistent recurrence (R11-proven mapping), coalesced + conflict-free,
// with h-load double-buffering and a two-level barrier tree.
// 128 blocks x 512 threads. Block bx owns cols j0 = bx*8.
// Thread (bg = tid>>5, lane): 4 batches x 8 cols; lane's k-set is the
// interleaved set {4*lane + 128*i + c} (coalesced warp h-loads).
// W in smem: addr_u64(k,jp) = k*4 + (k>>2)*2 + jp (phase-bank-balanced).
// ===========================================================================
__global__ __launch_bounds__(512, 1) void rnn_persistent_kernel(
    const float* __restrict__ h0, const float* __restrict__ Whh,
    float* __restrict__ out, int write_tail)
{
    __shared__ __align__(16) ull Ws2[4616];   // 36928 B

    const int tid = threadIdx.x;
    const int bx  = blockIdx.x;
    const int j0  = bx * 8;

    // One-time Whh slice load into skewed layout:
    // Ws2[k*4 + (k>>2)*2 + jp] = (W[j0+2jp][k], W[j0+2jp+1][k])
    {
        const int k = tid * 2;                     // k, k+1 share a quad
        const int base = k * 4 + (k >> 2) * 2;
        #pragma unroll
        for (int jp = 0; jp < 4; jp++) {
            float2 wa = *(const float2*)(Whh + (size_t)(j0 + 2 * jp) * D_H + k);
            float2 wb = *(const float2*)(Whh + (size_t)(j0 + 2 * jp + 1) * D_H + k);
            Ws2[base + jp]     = pk2(wa.x, wb.x);
            Ws2[base + 4 + jp] = pk2(wa.y, wb.y);
        }
    }
    __syncthreads();

    const int bg   = tid >> 5;        // 0..15 batch group
    const int lane = tid & 31;
    const int b0   = bg * 4;
    const ull* wl  = Ws2 + 18 * lane; // lane base of the skewed layout

    // after reduction, lane l owns output (b0 + (l>>3), j0 + (l&7))
    const int oidx = (b0 + (lane >> 3)) * D_H + j0 + (lane & 7);
    const unsigned grp = (unsigned)(bx >> 4);     // 16 blocks per group

    for (int t = 0; t < SEQ; t++) {
        const float* hsrc = (t == 0) ? h0 : out + (size_t)(t - 1) * BH;
        float* op = out + (size_t)t * BH + oidx;

        // prefetch xproj early (off the critical path)
        float xp = __ldcg(op);

        ull acc[4][4];                // [bb][jp]
        #pragma unroll
        for (int bb = 0; bb < 4; bb++)
            #pragma unroll
            for (int jp = 0; jp < 4; jp++) acc[bb][jp] = 0ull;

        // software-pipelined h loads: hv = current, hvn = next
        float4 hv[4], hvn[4];
        #pragma unroll
        for (int bb = 0; bb < 4; bb++)
            hv[bb] = __ldcg((const float4*)(hsrc + (size_t)(b0 + bb) * D_H + lane * 4));

        #pragma unroll
        for (int i = 0; i < 8; i++) {
            if (i < 7) {
                #pragma unroll
                for (int bb = 0; bb < 4; bb++)
                    hvn[bb] = __ldcg((const float4*)(hsrc + (size_t)(b0 + bb) * D_H
                                                     + (i + 1) * 128 + lane * 4));
            }
            const ull* wi = wl + 576 * i;
            #pragma unroll
            for (int c = 0; c < 4; c++) {          // k = 4*lane + 128*i + c
                ulonglong2 wA = *(const ulonglong2*)(wi + 4 * c);
                ulonglong2 wB = *(const ulonglong2*)(wi + 4 * c + 2);
                #pragma unroll
                for (int bb = 0; bb < 4; bb++) {
                    float hk = ((const float*)&hv[bb])[c];
                    ull h2 = pk2(hk, hk);
                    acc[bb][0] = fma2(h2, wA.x, acc[bb][0]);
                    acc[bb][1] = fma2(h2, wA.y, acc[bb][1]);
                    acc[bb][2] = fma2(h2, wB.x, acc[bb][2]);
                    acc[bb][3] = fma2(h2, wB.y, acc[bb][3]);
                }
            }
            #pragma unroll
            for (int bb = 0; bb < 4; bb++) hv[bb] = hvn[bb];
        }

        // unpack to v[a], a = bb*8 + col (col = 2*jp + p)
        float v[32];
        #pragma unroll
        for (int bb = 0; bb < 4; bb++)
            #pragma unroll
            for (int jp = 0; jp < 4; jp++)
                upk2(v[bb * 8 + 2 * jp], v[bb * 8 + 2 * jp + 1], acc[bb][jp]);

        // halving butterfly: lane l ends with the full sum of v[l]
        #pragma unroll
        for (int s = 0; s < 5; s++) {
            const int m = 16 >> s;         // 16,8,4,2,1
            const bool hi = (lane & m) != 0;
            #pragma unroll
            for (int q = 0; q < 16; q++) { // only q < m is live
                if (q < m) {
                    float tsend = hi ? v[q] : v[q + m];
                    float r = __shfl_xor_sync(0xffffffffu, tsend, m);
                    v[q] = (hi ? v[q + m] : v[q]) + r;
                }
            }
        }

        float hv_o = tanhf(xp + v[0]);
        __stcg(op, hv_o);
        if (write_tail && t == SEQ - 1) __stcg(out + (size_t)SEQ * BH + oidx, hv_o);

        // two-level grid barrier: group counters + root, absolute targets
        if (t < SEQ - 1) {
            __threadfence();
            __syncthreads();
            if (tid == 0) {
                unsigned v0 = atomicAdd(&g_grp[grp * 64], 1u) + 1u;
                if (v0 == (unsigned)(t + 1) * 16u)       // last in group
                    atomicAdd(&g_root, 1u);
                const unsigned target = (unsigned)(t + 1) * NGRP;
                while (*((volatile unsigned*)&g_root) < target) { }
            }
            __syncthreads();
        }
    }
}

// ===========================================================================
extern "C" void kernel_launch(void* const* d_in, const int* in_sizes, int n_in,
                              void* d_out, int out_size) {
    const float* x   = (const float*)d_in[0];
    const float* h0  = (const float*)d_in[1];
    const float* Wih = (const float*)d_in[2];
    const float* bih = (const float*)d_in[3];
    const float* Whh = (const float*)d_in[4];
    const float* bhh = (const float*)d_in[5];
    float* out = (float*)d_out;

    input_gemm_kernel<<<dim3(D_H / 128, M_IN / 128), 256>>>(x, Wih, bih, bhh, out);

    long long total = (long long)SEQ * BH;
    int write_tail = ((long long)out_size >= total + BH) ? 1 : 0;
    rnn_persistent_kernel<<<GRID_P, 512>>>(h0, Whh, out, write_tail);
}

// round 13
// speedup vs baseline: 1.0491x; 1.0491x over previous
#include <cuda_runtime.h>
#include <cuda_bf16.h>
#include <math.h>
#include <stdint.h>

#define SEQ    512
#define BATCH  64
#define D_IN   1024
#define D_H    1024
#define M_IN   (SEQ * BATCH)      // 32768
#define BH     (BATCH * D_H)      // 65536
#define GRID_P 128                // persistent blocks for recurrence

typedef unsigned long long ull;

// packed f32x2 helpers (FFMA2: only reachable via PTX fma.rn.f32x2)
__device__ __forceinline__ ull pk2(float lo, float hi) {
    ull r;
    asm("mov.b64 %0, {%1, %2};" : "=l"(r) : "r"(__float_as_uint(lo)), "r"(__float_as_uint(hi)));
    return r;
}
__device__ __forceinline__ void upk2(float& lo, float& hi, ull v) {
    uint32_t a, b;
    asm("mov.b64 {%0, %1}, %2;" : "=r"(a), "=r"(b) : "l"(v));
    lo = __uint_as_float(a); hi = __uint_as_float(b);
}
__device__ __forceinline__ ull fma2(ull a, ull b, ull c) {
    ull d;
    asm("fma.rn.f32x2 %0, %1, %2, %3;" : "=l"(d) : "l"(a), "l"(b), "l"(c));
    return d;
}

// ===========================================================================
// Persistent device state: barrier counter. Reset to 0 by the GEMM kernel
// (stream-ordered before the rnn kernel), so every run uses absolute targets.
// ===========================================================================
__device__ unsigned g_count;

// ===========================================================================
// Input projection: out[m][n] = sum_i x[m][i]*Wih[n][i] + bih[n] + bhh[n]
// M=32768, N=1024, K=1024. BM=BN=128, BK=16, 8x8 thread tile, 256 threads.
// Double-buffered smem: ONE __syncthreads per k-tile; global loads and smem
// stores for tile kt+1 overlap the 16-k FMA loop on tile kt.
// Block (0,0) resets the rnn barrier counter.
// ===========================================================================
__global__ __launch_bounds__(256) void input_gemm_kernel(
    const float* __restrict__ x, const float* __restrict__ Wih,
    const float* __restrict__ bih, const float* __restrict__ bhh,
    float* __restrict__ out)
{
    __shared__ __align__(16) float As[2][16][132];
    __shared__ __align__(16) float Bs[2][16][132];

    const int tid = threadIdx.x;
    if (blockIdx.x == 0 && blockIdx.y == 0 && tid == 0) g_count = 0u;

    const int m0 = blockIdx.y * 128;
    const int n0 = blockIdx.x * 128;
    const int tx = tid & 15;   // -> n
    const int ty = tid >> 4;   // -> m

    // per-thread load coordinates (2 float4 each for A and B per tile)
    int lr[2], lc[2];
    #pragma unroll
    for (int l = 0; l < 2; l++) {
        int f = tid + l * 256;
        lr[l] = f >> 2;
        lc[l] = (f & 3) * 4;
    }

    ull acc2[8][4];
    #pragma unroll
    for (int i = 0; i < 8; i++)
        #pragma unroll
        for (int j = 0; j < 4; j++) acc2[i][j] = 0ull;

    // prologue: load tile 0 into buffer 0
    #pragma unroll
    for (int l = 0; l < 2; l++) {
        float4 vA = *(const float4*)(x   + (size_t)(m0 + lr[l]) * D_IN + lc[l]);
        float4 vB = *(const float4*)(Wih + (size_t)(n0 + lr[l]) * D_IN + lc[l]);
        int r = lr[l], c = lc[l];
        As[0][c + 0][r] = vA.x; As[0][c + 1][r] = vA.y;
        As[0][c + 2][r] = vA.z; As[0][c + 3][r] = vA.w;
        Bs[0][c + 0][r] = vB.x; Bs[0][c + 1][r] = vB.y;
        Bs[0][c + 2][r] = vB.z; Bs[0][c + 3][r] = vB.w;
    }
    __syncthreads();

    const int NT = D_IN / 16;   // 64 tiles
    for (int kt = 0; kt < NT; kt++) {
        const int cur = kt & 1, nxt = cur ^ 1;

        // prefetch next tile into registers (overlaps the FMA loop)
        float4 pA[2], pB[2];
        if (kt < NT - 1) {
            const int k0 = (kt + 1) * 16;
            #pragma unroll
            for (int l = 0; l < 2; l++) {
                pA[l] = *(const float4*)(x   + (size_t)(m0 + lr[l]) * D_IN + k0 + lc[l]);
                pB[l] = *(const float4*)(Wih + (size_t)(n0 + lr[l]) * D_IN + k0 + lc[l]);
            }
        }

        #pragma unroll
        for (int k = 0; k < 16; k++) {
            float a[8], b[8];
            *(float4*)&a[0] = *(const float4*)&As[cur][k][ty * 8];
            *(float4*)&a[4] = *(const float4*)&As[cur][k][ty * 8 + 4];
            *(float4*)&b[0] = *(const float4*)&Bs[cur][k][tx * 8];
            *(float4*)&b[4] = *(const float4*)&Bs[cur][k][tx * 8 + 4];
            ull b2[4];
            #pragma unroll
            for (int q = 0; q < 4; q++) b2[q] = pk2(b[2 * q], b[2 * q + 1]);
            #pragma unroll
            for (int i = 0; i < 8; i++) {
                ull a2 = pk2(a[i], a[i]);
                #pragma unroll
                for (int q = 0; q < 4; q++)
                    acc2[i][q] = fma2(a2, b2[q], acc2[i][q]);
            }
        }

        // stage next tile into the other buffer; one sync per tile.
        // (buffer reuse distance = 2 iterations -> single sync is sufficient)
        if (kt < NT - 1) {
            #pragma unroll
            for (int l = 0; l < 2; l++) {
                int r = lr[l], c = lc[l];
                As[nxt][c + 0][r] = pA[l].x; As[nxt][c + 1][r] = pA[l].y;
                As[nxt][c + 2][r] = pA[l].z; As[nxt][c + 3][r] = pA[l].w;
                Bs[nxt][c + 0][r] = pB[l].x; Bs[nxt][c + 1][r] = pB[l].y;
                Bs[nxt][c + 2][r] = pB[l].z; Bs[nxt][c + 3][r] = pB[l].w;
            }
            __syncthreads();
        }
    }

    #pragma unroll
    for (int i = 0; i < 8; i++) {
        int m = m0 + ty * 8 + i;
        float accf[8];
        #pragma unroll
        for (int q = 0; q < 4; q++) upk2(accf[2 * q], accf[2 * q + 1], acc2[i][q]);
        #pragma unroll
        for (int j = 0; j < 8; j += 4) {
            int n = n0 + tx * 8 + j;
            float4 o;
            o.x = accf[j + 0] + bih[n + 0] + bhh[n + 0];
            o.y = accf[j + 1] + bih[n + 1] + bhh[n + 1];
            o.z = accf[j + 2] + bih[n + 2] + bhh[n + 2];
            o.w = accf[j + 3] + bih[n + 3] + bhh[n + 3];
            *(float4*)(out + (size_t)m * D_H + n) = o;
        }
    }
}

// ===========================================================================
// Persistent recurrence (R11-proven), coalesced + conflict-free.
// 128 blocks x 512 threads. Block bx owns cols j0 = bx*8.
// Thread (bg = tid>>5, lane): 4 batches x 8 cols; lane's k-set is the
// interleaved set {4*lane + 128*i + c} (coalesced warp h-loads).
// W in smem: addr_u64(k,jp) = k*4 + (k>>2)*2 + jp (phase-bank-balanced).
// xproj for step t+1 prefetched before the barrier wait.
// ===========================================================================
__global__ __launch_bounds__(512, 1) void rnn_persistent_kernel(
    const float* __restrict__ h0, const float* __restrict__ Whh,
    float* __restrict__ out, int write_tail)
{
    __shared__ __align__(16) ull Ws2[4616];   // 36928 B

    const int tid = threadIdx.x;
    const int bx  = blockIdx.x;
    const int j0  = bx * 8;

    // One-time Whh slice load into skewed layout:
    // Ws2[k*4 + (k>>2)*2 + jp] = (W[j0+2jp][k], W[j0+2jp+1][k])
    {
        const int k = tid * 2;                     // k, k+1 share a quad
        const int base = k * 4 + (k >> 2) * 2;
        #pragma unroll
        for (int jp = 0; jp < 4; jp++) {
            float2 wa = *(const float2*)(Whh + (size_t)(j0 + 2 * jp) * D_H + k);
            float2 wb = *(const float2*)(Whh + (size_t)(j0 + 2 * jp + 1) * D_H + k);
            Ws2[base + jp]     = pk2(wa.x, wb.x);
            Ws2[base + 4 + jp] = pk2(wa.y, wb.y);
        }
    }
    __syncthreads();

    const int bg   = tid >> 5;        // 0..15 batch group
    const int lane = tid & 31;
    const int b0   = bg * 4;
    const ull* wl  = Ws2 + 18 * lane; // lane base of the skewed layout

    // after reduction, lane l owns output (b0 + (l>>3), j0 + (l&7))
    const int oidx = (b0 + (lane >> 3)) * D_H + j0 + (lane & 7);

    // prefetch xproj of step 0
    float xp = __ldcg(out + oidx);

    for (int t = 0; t < SEQ; t++) {
        const float* hsrc = (t == 0) ? h0 : out + (size_t)(t - 1) * BH;
        float* op = out + (size_t)t * BH + oidx;

        ull acc[4][4];                // [bb][jp]
        #pragma unroll
        for (int bb = 0; bb < 4; bb++)
            #pragma unroll
            for (int jp = 0; jp < 4; jp++) acc[bb][jp] = 0ull;

        #pragma unroll
        for (int i = 0; i < 8; i++) {
            // warp-coalesced: lanes read 32 consecutive float4 of one batch row
            float4 hv[4];
            #pragma unroll
            for (int bb = 0; bb < 4; bb++)
                hv[bb] = __ldcg((const float4*)(hsrc + (size_t)(b0 + bb) * D_H
                                                + i * 128 + lane * 4));
            const ull* wi = wl + 576 * i;
            #pragma unroll
            for (int c = 0; c < 4; c++) {          // k = 4*lane + 128*i + c
                ulonglong2 wA = *(const ulonglong2*)(wi + 4 * c);
                ulonglong2 wB = *(const ulonglong2*)(wi + 4 * c + 2);
                #pragma unroll
                for (int bb = 0; bb < 4; bb++) {
                    float hk = ((const float*)&hv[bb])[c];
                    ull h2 = pk2(hk, hk);
                    acc[bb][0] = fma2(h2, wA.x, acc[bb][0]);
                    acc[bb][1] = fma2(h2, wA.y, acc[bb][1]);
                    acc[bb][2] = fma2(h2, wB.x, acc[bb][2]);
                    acc[bb][3] = fma2(h2, wB.y, acc[bb][3]);
                }
            }
        }

        // unpack to v[a], a = bb*8 + col (col = 2*jp + p)
        float v[32];
        #pragma unroll
        for (int bb = 0; bb < 4; bb++)
            #pragma unroll
            for (int jp = 0; jp < 4; jp++)
                upk2(v[bb * 8 + 2 * jp], v[bb * 8 + 2 * jp + 1], acc[bb][jp]);

        // halving butterfly: lane l ends with the full sum of v[l]
        #pragma unroll
        for (int s = 0; s < 5; s++) {
            const int m = 16 >> s;         // 16,8,4,2,1
            const bool hi = (lane & m) != 0;
            #pragma unroll
            for (int q = 0; q < 16; q++) { // only q < m is live
                if (q < m) {
                    float tsend = hi ? v[q] : v[q + m];
                    float r = __shfl_xor_sync(0xffffffffu, tsend, m);
                    v[q] = (hi ? v[q + m] : v[q]) + r;
                }
            }
        }

        float hv_o = tanhf(xp + v[0]);
        __stcg(op, hv_o);
        if (write_tail && t == SEQ - 1) __stcg(out + (size_t)SEQ * BH + oidx, hv_o);

        // prefetch next step's xproj (GEMM-written; only this thread will
        // overwrite it, at step t+1) BEFORE the barrier -> latency hidden
        if (t < SEQ - 1) {
            xp = __ldcg(out + (size_t)(t + 1) * BH + oidx);

            // grid barrier: absolute target, 1 atomic + 1 poller per block
            __threadfence();
            __syncthreads();
            if (tid == 0) {
                const unsigned target = (unsigned)(t + 1) * GRID_P;
                atomicAdd(&g_count, 1u);
                while (*((volatile unsigned*)&g_count) < target) { }
            }
            __syncthreads();
        }
    }
}

// ===========================================================================
extern "C" void kernel_launch(void* const* d_in, const int* in_sizes, int n_in,
                              void* d_out, int out_size) {
    const float* x   = (const float*)d_in[0];
    const float* h0  = (const float*)d_in[1];
    const float* Wih = (const float*)d_in[2];
    const float* bih = (const float*)d_in[3];
    const float* Whh = (const float*)d_in[4];
    const float* bhh = (const float*)d_in[5];
    float* out = (float*)d_out;

    input_gemm_kernel<<<dim3(D_H / 128, M_IN / 128), 256>>>(x, Wih, bih, bhh, out);

    long long total = (long long)SEQ * BH;
    int write_tail = ((long long)out_size >= total + BH) ? 1 : 0;
    rnn_persistent_kernel<<<GRID_P, 512>>>(h0, Whh, out, write_tail);
}

// round 15
// speedup vs baseline: 1.0598x; 1.0102x over previous
#include <cuda_runtime.h>
#include <cuda_bf16.h>
#include <math.h>
#include <stdint.h>

#define SEQ    512
#define BATCH  64
#define D_IN   1024
#define D_H    1024
#define M_IN   (SEQ * BATCH)      // 32768
#define BH     (BATCH * D_H)      // 65536
#define GRID_P 128                // persistent blocks for recurrence
#define NGRP   4                  // independent batch groups
#define GRPSZ  32                 // blocks per group (split 1024 cols)
#define REGU   4616               // u64 per 8-col skewed W region
#define SMEM_RNN (4 * REGU * 8)   // 147712 B dynamic smem

typedef unsigned long long ull;

// packed f32x2 helpers (FFMA2: only reachable via PTX fma.rn.f32x2)
__device__ __forceinline__ ull pk2(float lo, float hi) {
    ull r;
    asm("mov.b64 %0, {%1, %2};" : "=l"(r) : "r"(__float_as_uint(lo)), "r"(__float_as_uint(hi)));
    return r;
}
__device__ __forceinline__ void upk2(float& lo, float& hi, ull v) {
    uint32_t a, b;
    asm("mov.b64 {%0, %1}, %2;" : "=r"(a), "=r"(b) : "l"(v));
    lo = __uint_as_float(a); hi = __uint_as_float(b);
}
__device__ __forceinline__ ull fma2(ull a, ull b, ull c) {
    ull d;
    asm("fma.rn.f32x2 %0, %1, %2, %3;" : "=l"(d) : "l"(a), "l"(b), "l"(c));
    return d;
}

// ===========================================================================
// Persistent device state: per-group barrier counters (256B-strided -> own
// L2 lines). Reset by the GEMM kernel (stream-ordered before rnn), so every
// run uses absolute targets.
// ===========================================================================
__device__ unsigned g_cnt[NGRP * 64];

// ===========================================================================
// Input projection: out[m][n] = sum_i x[m][i]*Wih[n][i] + bih[n] + bhh[n]
// M=32768, N=1024, K=1024. BM=BN=128, BK=16, 8x8 thread tile, 256 threads.
// Double-buffered smem, one sync per tile (R13-proven).
// Block (0,0) resets the rnn group counters.
// ===========================================================================
__global__ __launch_bounds__(256) void input_gemm_kernel(
    const float* __restrict__ x, const float* __restrict__ Wih,
    const float* __restrict__ bih, const float* __restrict__ bhh,
    float* __restrict__ out)
{
    __shared__ __align__(16) float As[2][16][132];
    __shared__ __align__(16) float Bs[2][16][132];

    const int tid = threadIdx.x;
    if (blockIdx.x == 0 && blockIdx.y == 0 && tid < NGRP) g_cnt[tid * 64] = 0u;

    const int m0 = blockIdx.y * 128;
    const int n0 = blockIdx.x * 128;
    const int tx = tid & 15;   // -> n
    const int ty = tid >> 4;   // -> m

    int lr[2], lc[2];
    #pragma unroll
    for (int l = 0; l < 2; l++) {
        int f = tid + l * 256;
        lr[l] = f >> 2;
        lc[l] = (f & 3) * 4;
    }

    ull acc2[8][4];
    #pragma unroll
    for (int i = 0; i < 8; i++)
        #pragma unroll
        for (int j = 0; j < 4; j++) acc2[i][j] = 0ull;

    #pragma unroll
    for (int l = 0; l < 2; l++) {
        float4 vA = *(const float4*)(x   + (size_t)(m0 + lr[l]) * D_IN + lc[l]);
        float4 vB = *(const float4*)(Wih + (size_t)(n0 + lr[l]) * D_IN + lc[l]);
        int r = lr[l], c = lc[l];
        As[0][c + 0][r] = vA.x; As[0][c + 1][r] = vA.y;
        As[0][c + 2][r] = vA.z; As[0][c + 3][r] = vA.w;
        Bs[0][c + 0][r] = vB.x; Bs[0][c + 1][r] = vB.y;
        Bs[0][c + 2][r] = vB.z; Bs[0][c + 3][r] = vB.w;
    }
    __syncthreads();

    const int NT = D_IN / 16;   // 64 tiles
    for (int kt = 0; kt < NT; kt++) {
        const int cur = kt & 1, nxt = cur ^ 1;

        float4 pA[2], pB[2];
        if (kt < NT - 1) {
            const int k0 = (kt + 1) * 16;
            #pragma unroll
            for (int l = 0; l < 2; l++) {
                pA[l] = *(const float4*)(x   + (size_t)(m0 + lr[l]) * D_IN + k0 + lc[l]);
                pB[l] = *(const float4*)(Wih + (size_t)(n0 + lr[l]) * D_IN + k0 + lc[l]);
            }
        }

        #pragma unroll
        for (int k = 0; k < 16; k++) {
            float a[8], b[8];
            *(float4*)&a[0] = *(const float4*)&As[cur][k][ty * 8];
            *(float4*)&a[4] = *(const float4*)&As[cur][k][ty * 8 + 4];
            *(float4*)&b[0] = *(const float4*)&Bs[cur][k][tx * 8];
            *(float4*)&b[4] = *(const float4*)&Bs[cur][k][tx * 8 + 4];
            ull b2[4];
            #pragma unroll
            for (int q = 0; q < 4; q++) b2[q] = pk2(b[2 * q], b[2 * q + 1]);
            #pragma unroll
            for (int i = 0; i < 8; i++) {
                ull a2 = pk2(a[i], a[i]);
                #pragma unroll
                for (int q = 0; q < 4; q++)
                    acc2[i][q] = fma2(a2, b2[q], acc2[i][q]);
            }
        }

        if (kt < NT - 1) {
            #pragma unroll
            for (int l = 0; l < 2; l++) {
                int r = lr[l], c = lc[l];
                As[nxt][c + 0][r] = pA[l].x; As[nxt][c + 1][r] = pA[l].y;
                As[nxt][c + 2][r] = pA[l].z; As[nxt][c + 3][r] = pA[l].w;
                Bs[nxt][c + 0][r] = pB[l].x; Bs[nxt][c + 1][r] = pB[l].y;
                Bs[nxt][c + 2][r] = pB[l].z; Bs[nxt][c + 3][r] = pB[l].w;
            }
            __syncthreads();
        }
    }

    #pragma unroll
    for (int i = 0; i < 8; i++) {
        int m = m0 + ty * 8 + i;
        float accf[8];
        #pragma unroll
        for (int q = 0; q < 4; q++) upk2(accf[2 * q], accf[2 * q + 1], acc2[i][q]);
        #pragma unroll
        for (int j = 0; j < 8; j += 4) {
            int n = n0 + tx * 8 + j;
            float4 o;
            o.x = accf[j + 0] + bih[n + 0] + bhh[n + 0];
            o.y = accf[j + 1] + bih[n + 1] + bhh[n + 1];
            o.z = accf[j + 2] + bih[n + 2] + bhh[n + 2];
            o.w = accf[j + 3] + bih[n + 3] + bhh[n + 3];
            *(float4*)(out + (size_t)m * D_H + n) = o;
        }
    }
}

// ===========================================================================
// Persistent recurrence, batch-grouped: NO global barrier.
// 4 independent groups x 32 blocks. Group g owns batches [g*16, g*16+16);
// block s within group computes cols [s*32, s*32+32) for those batches.
// Each block caches its 32x1024 W slice in dynamic smem (4 skewed 8-col
// regions, R11-proven layout). Warp (wb, wc) = 4 batches x 8 cols; lane
// k-set is the interleaved {4l + 128i + c} (coalesced h loads).
// Per-step sync: 32-block per-group atomic counter (absolute targets).
// h state lives in out: step t reads out[t-1] (t=0: h0).
// ===========================================================================
__global__ __launch_bounds__(512, 1) void rnn_persistent_kernel(
    const float* __restrict__ h0, const float* __restrict__ Whh,
    float* __restrict__ out, int write_tail)
{
    extern __shared__ __align__(16) ull Ws2[];   // 4 * 4616 u64

    const int tid  = threadIdx.x;
    const int bx   = blockIdx.x;
    const int g    = bx >> 5;         // group 0..3
    const int s    = bx & 31;         // col-block within group
    const int wid  = tid >> 5;
    const int lane = tid & 31;

    // One-time W load: warp w covers region r = w&3 (cols s*32 + r*8 ..+8),
    // k-quarter kq = w>>2; lane covers 8 k. Skew: addr_u64 = k*4+(k>>2)*2+jp.
    {
        const int r  = wid & 3;
        const int kq = wid >> 2;
        const int j0w = s * 32 + r * 8;
        ull* reg = Ws2 + r * REGU;
        #pragma unroll
        for (int kk = 0; kk < 8; kk += 2) {
            const int k = kq * 256 + lane * 8 + kk;
            const int base = k * 4 + (k >> 2) * 2;
            #pragma unroll
            for (int jp = 0; jp < 4; jp++) {
                float2 wa = *(const float2*)(Whh + (size_t)(j0w + 2 * jp) * D_H + k);
                float2 wb = *(const float2*)(Whh + (size_t)(j0w + 2 * jp + 1) * D_H + k);
                reg[base + jp]     = pk2(wa.x, wb.x);
                reg[base + 4 + jp] = pk2(wa.y, wb.y);
            }
        }
    }
    __syncthreads();

    const int wb = wid >> 2;          // batch sub-group 0..3
    const int wc = wid & 3;           // col region 0..3
    const int b0 = g * 16 + wb * 4;   // 4 batches
    const int j0c = s * 32 + wc * 8;  // 8 cols
    const ull* wl = Ws2 + wc * REGU + 18 * lane;

    // after butterfly, lane l owns output (b0 + (l>>3), j0c + (l&7))
    const int oidx = (b0 + (lane >> 3)) * D_H + j0c + (lane & 7);
    unsigned* const cnt = &g_cnt[g * 64];

    // prefetch xproj of step 0
    float xp = __ldcg(out + oidx);

    for (int t = 0; t < SEQ; t++) {
        const float* hsrc = (t == 0) ? h0 : out + (size_t)(t - 1) * BH;
        float* op = out + (size_t)t * BH + oidx;

        ull acc[4][4];                // [bb][jp]
        #pragma unroll
        for (int bb = 0; bb < 4; bb++)
            #pragma unroll
            for (int jp = 0; jp < 4; jp++) acc[bb][jp] = 0ull;

        #pragma unroll
        for (int i = 0; i < 8; i++) {
            float4 hv[4];
            #pragma unroll
            for (int bb = 0; bb < 4; bb++)
                hv[bb] = __ldcg((const float4*)(hsrc + (size_t)(b0 + bb) * D_H
                                                + i * 128 + lane * 4));
            const ull* wi = wl + 576 * i;
            #pragma unroll
            for (int c = 0; c < 4; c++) {          // k = 4*lane + 128*i + c
                ulonglong2 wA = *(const ulonglong2*)(wi + 4 * c);
                ulonglong2 wB = *(const ulonglong2*)(wi + 4 * c + 2);
                #pragma unroll
                for (int bb = 0; bb < 4; bb++) {
                    float hk = ((const float*)&hv[bb])[c];
                    ull h2 = pk2(hk, hk);
                    acc[bb][0] = fma2(h2, wA.x, acc[bb][0]);
                    acc[bb][1] = fma2(h2, wA.y, acc[bb][1]);
                    acc[bb][2] = fma2(h2, wB.x, acc[bb][2]);
                    acc[bb][3] = fma2(h2, wB.y, acc[bb][3]);
                }
            }
        }

        float v[32];
        #pragma unroll
        for (int bb = 0; bb < 4; bb++)
            #pragma unroll
            for (int jp = 0; jp < 4; jp++)
                upk2(v[bb * 8 + 2 * jp], v[bb * 8 + 2 * jp + 1], acc[bb][jp]);

        // halving butterfly: lane l ends with the full sum of v[l]
        #pragma unroll
        for (int st = 0; st < 5; st++) {
            const int m = 16 >> st;        // 16,8,4,2,1
            const bool hi = (lane & m) != 0;
            #pragma unroll
            for (int q = 0; q < 16; q++) { // only q < m is live
                if (q < m) {
                    float tsend = hi ? v[q] : v[q + m];
                    float r2 = __shfl_xor_sync(0xffffffffu, tsend, m);
                    v[q] = (hi ? v[q + m] : v[q]) + r2;
                }
            }
        }

        float hv_o = tanhf(xp + v[0]);
        __stcg(op, hv_o);
        if (write_tail && t == SEQ - 1) __stcg(out + (size_t)SEQ * BH + oidx, hv_o);

        // per-group barrier (32 blocks): absolute target, reset by GEMM
        if (t < SEQ - 1) {
            xp = __ldcg(out + (size_t)(t + 1) * BH + oidx);  // prefetch next xproj
            __threadfence();
            __syncthreads();
            if (tid == 0) {
                const unsigned target = (unsigned)(t + 1) * GRPSZ;
                atomicAdd(cnt, 1u);
                while (*((volatile unsigned*)cnt) < target) { }
            }
            __syncthreads();
        }
    }
}

// ===========================================================================
extern "C" void kernel_launch(void* const* d_in, const int* in_sizes, int n_in,
                              void* d_out, int out_size) {
    const float* x   = (const float*)d_in[0];
    const float* h0  = (const float*)d_in[1];
    const float* Wih = (const float*)d_in[2];
    const float* bih = (const float*)d_in[3];
    const float* Whh = (const float*)d_in[4];
    const float* bhh = (const float*)d_in[5];
    float* out = (float*)d_out;

    cudaFuncSetAttribute(rnn_persistent_kernel,
                         cudaFuncAttributeMaxDynamicSharedMemorySize, SMEM_RNN);

    input_gemm_kernel<<<dim3(D_H / 128, M_IN / 128), 256>>>(x, Wih, bih, bhh, out);

    long long total = (long long)SEQ * BH;
    int write_tail = ((long long)out_size >= total + BH) ? 1 : 0;
    rnn_persistent_kernel<<<GRID_P, 512, SMEM_RNN>>>(h0, Whh, out, write_tail);
}